// round 16
// baseline (speedup 1.0000x reference)
#include <cuda_runtime.h>
#include <cuda_bf16.h>
#include <cstdint>

#define BB 8
#define CC 256
#define MM 2048
#define NN 4096
#define C3 768
#define HH 384
#define OUT_D 128
#define KNN_K 3

typedef __nv_bfloat16 bf16;

// ---------------- device scratch ----------------
__device__ float g_rt[BB * MM * 3];
__device__ float g_rr[BB * MM];
__device__ bf16  g_Fhi[(size_t)BB * C3 * MM];
__device__ bf16  g_Flo[(size_t)BB * C3 * MM];
__device__ bf16  g_W1hi[HH * C3];
__device__ bf16  g_W1lo[HH * C3];
__device__ bf16  g_W2hi[OUT_D * HH];
__device__ bf16  g_W2lo[OUT_D * HH];
__device__ float g_Zt[BB * MM * HH];
__device__ bf16  g_hhi[(size_t)BB * NN * HH];
__device__ bf16  g_hlo[(size_t)BB * NN * HH];

// ---------------- ptx helpers (all sm_80+ baseline, no "a" features) -------
__device__ __forceinline__ uint32_t smem_u32(const void* p) {
    uint32_t a;
    asm("{ .reg .u64 t; cvta.to.shared.u64 t, %1; cvt.u32.u64 %0, t; }" : "=r"(a) : "l"(p));
    return a;
}
#define CP_ASYNC16(saddr, gptr) \
    asm volatile("cp.async.cg.shared.global [%0], [%1], 16;" :: "r"(saddr), "l"(gptr))
#define CP_COMMIT() asm volatile("cp.async.commit_group;" ::: "memory")
#define CP_WAIT1()  asm volatile("cp.async.wait_group 1;" ::: "memory")
#define CP_WAIT2()  asm volatile("cp.async.wait_group 2;" ::: "memory")

__device__ __forceinline__ void ldsm_x4(uint32_t* r, uint32_t addr) {
    asm volatile("ldmatrix.sync.aligned.m8n8.x4.shared.b16 {%0,%1,%2,%3}, [%4];"
                 : "=r"(r[0]), "=r"(r[1]), "=r"(r[2]), "=r"(r[3]) : "r"(addr));
}
__device__ __forceinline__ void ldsm_x4_t(uint32_t* r, uint32_t addr) {
    asm volatile("ldmatrix.sync.aligned.m8n8.x4.trans.shared.b16 {%0,%1,%2,%3}, [%4];"
                 : "=r"(r[0]), "=r"(r[1]), "=r"(r[2]), "=r"(r[3]) : "r"(addr));
}
__device__ __forceinline__ void mma16816(float* d, const uint32_t* a, const uint32_t* b) {
    asm volatile(
        "mma.sync.aligned.m16n8k16.row.col.f32.bf16.bf16.f32 "
        "{%0,%1,%2,%3}, {%4,%5,%6,%7}, {%8,%9}, {%0,%1,%2,%3};"
        : "+f"(d[0]), "+f"(d[1]), "+f"(d[2]), "+f"(d[3])
        : "r"(a[0]), "r"(a[1]), "r"(a[2]), "r"(a[3]), "r"(b[0]), "r"(b[1]));
}

// ======================= prep: featrot + wsplitW1 + wsplitW2 + rot =========
// block ranges: [0,4096) featrot | [4096,5248) W1 split | [5248,5440) W2 split
//               [5440,5504) xyz rot
#define PREP_FEAT_BLOCKS 4096
#define PREP_W1_BLOCKS   1152
#define PREP_W2_BLOCKS   192
#define PREP_ROT_BLOCKS  64
#define PREP_GRID (PREP_FEAT_BLOCKS + PREP_W1_BLOCKS + PREP_W2_BLOCKS + PREP_ROT_BLOCKS)
__global__ void prep_kernel(const float* __restrict__ vf, const float* __restrict__ xyz,
                            const float* __restrict__ W1, const float* __restrict__ W2,
                            const float* __restrict__ Rg) {
    const int blk = blockIdx.x;
    const int tid = threadIdx.x;
    if (blk < PREP_FEAT_BLOCKS) {
        // featrot: rotate features, write bf16 hi/lo split (4 points/thread)
        int t = blk * 256 + tid;
        int p0 = t * 4;
        int b = p0 / (CC * MM);
        const float* R = Rg + b * 9;
        float R00 = R[0], R01 = R[1], R02 = R[2];
        float R10 = R[3], R11 = R[4], R12 = R[5];
        float R20 = R[6], R21 = R[7], R22 = R[8];
        const float4* src = (const float4*)(vf + (size_t)p0 * 3);
        float4 v0 = src[0], v1 = src[1], v2 = src[2];
        float px[4] = {v0.x, v0.w, v1.z, v2.y};
        float py[4] = {v0.y, v1.x, v1.w, v2.z};
        float pz[4] = {v0.z, v1.y, v2.x, v2.w};
        float o[12];
#pragma unroll
        for (int p = 0; p < 4; p++) {
            o[p * 3 + 0] = fmaf(pz[p], R20, fmaf(py[p], R10, px[p] * R00));
            o[p * 3 + 1] = fmaf(pz[p], R21, fmaf(py[p], R11, px[p] * R01));
            o[p * 3 + 2] = fmaf(pz[p], R22, fmaf(py[p], R12, px[p] * R02));
        }
        __nv_bfloat162 hi[6], lo[6];
#pragma unroll
        for (int j = 0; j < 6; j++) {
            float a = o[j * 2], bq = o[j * 2 + 1];
            bf16 ha = __float2bfloat16_rn(a), hb = __float2bfloat16_rn(bq);
            bf16 la = __float2bfloat16_rn(a - __bfloat162float(ha));
            bf16 lb = __float2bfloat16_rn(bq - __bfloat162float(hb));
            hi[j].x = ha; hi[j].y = hb;
            lo[j].x = la; lo[j].y = lb;
        }
        __nv_bfloat162* dh = (__nv_bfloat162*)(g_Fhi + (size_t)p0 * 3);
        __nv_bfloat162* dl = (__nv_bfloat162*)(g_Flo + (size_t)p0 * 3);
#pragma unroll
        for (int j = 0; j < 6; j++) { dh[j] = hi[j]; dl[j] = lo[j]; }
    } else if (blk < PREP_FEAT_BLOCKS + PREP_W1_BLOCKS) {
        int t = (blk - PREP_FEAT_BLOCKS) * 256 + tid;  // < HH*C3 exactly
        float x = W1[t];
        bf16 h = __float2bfloat16_rn(x);
        g_W1hi[t] = h;
        g_W1lo[t] = __float2bfloat16_rn(x - __bfloat162float(h));
    } else if (blk < PREP_FEAT_BLOCKS + PREP_W1_BLOCKS + PREP_W2_BLOCKS) {
        int t = (blk - PREP_FEAT_BLOCKS - PREP_W1_BLOCKS) * 256 + tid;  // < OUT_D*HH
        float x = W2[t];
        bf16 h = __float2bfloat16_rn(x);
        g_W2hi[t] = h;
        g_W2lo[t] = __float2bfloat16_rn(x - __bfloat162float(h));
    } else {
        int t = (blk - PREP_FEAT_BLOCKS - PREP_W1_BLOCKS - PREP_W2_BLOCKS) * 256 + tid;
        int b = t / MM, m = t % MM;
        const float* R = Rg + b * 9;
        float x0 = xyz[(b * 3 + 0) * MM + m];
        float x1 = xyz[(b * 3 + 1) * MM + m];
        float x2 = xyz[(b * 3 + 2) * MM + m];
        float r0 = fmaf(x2, R[6], fmaf(x1, R[3], x0 * R[0]));
        float r1 = fmaf(x2, R[7], fmaf(x1, R[4], x0 * R[1]));
        float r2 = fmaf(x2, R[8], fmaf(x1, R[5], x0 * R[2]));
        g_rt[t * 3 + 0] = r0;
        g_rt[t * 3 + 1] = r1;
        g_rt[t * 3 + 2] = r2;
        g_rr[t] = (r0 * r0 + r1 * r1) + r2 * r2;
    }
}

// ======================= GEMM1 (HMMA): Zt[m][h] = (W1 @ G)^T ===============
// (identical to round-15 passing version: swizzled layouts, 3-stage pipeline)
#define G1_STAGE 32768
#define G1_SMEM  (3 * G1_STAGE)
__global__ __launch_bounds__(256, 2) void gemm1_mma() {
    extern __shared__ char smem[];
    const uint32_t sbase = smem_u32(smem);
    const int tid = threadIdx.x;
    const int wid = tid >> 5, lane = tid & 31;
    const int wy = wid >> 1, wx = wid & 1;  // warp tile: 32h x 64m
    const int b = blockIdx.z;
    const int m0 = blockIdx.x * 128;
    const int h0 = blockIdx.y * 128;
    const size_t bF = (size_t)b * C3 * MM;

    float d[2][8][4];
#pragma unroll
    for (int ty = 0; ty < 2; ty++)
#pragma unroll
        for (int tx = 0; tx < 8; tx++)
#pragma unroll
            for (int j = 0; j < 4; j++) d[ty][tx][j] = 0.0f;

    const int C = C3 / 32;  // 24 chunks

    auto issue = [&](int c, int st) {
        const int kk = c * 32;
        const uint32_t stg = sbase + st * G1_STAGE;
#pragma unroll
        for (int i = 0; i < 4; i++) {  // A: W1 hi/lo, 1024 x 16B granules
            int u = tid + i * 256;
            int row = u >> 3, g = u & 7;
            int split = g >> 2, seg = g & 3;
            const bf16* gp = (split ? g_W1lo : g_W1hi) + (size_t)(h0 + row) * C3 + kk + seg * 8;
            CP_ASYNC16(stg + row * 128 + ((g ^ (row & 7)) * 16), gp);
        }
#pragma unroll
        for (int i = 0; i < 4; i++) {  // B: G hi/lo, 1024 x 16B granules
            int u = tid + i * 256;
            int split = u >> 9, idx = u & 511;
            int row = idx >> 4, cm = idx & 15;
            const bf16* gp = (split ? g_Flo : g_Fhi) + bF + (size_t)(kk + row) * MM + m0 + cm * 8;
            CP_ASYNC16(stg + 16384 + split * 8192 + row * 256 +
                       (((cm & 8) | ((cm & 7) ^ (row & 7))) * 16), gp);
        }
    };

    issue(0, 0); CP_COMMIT();
    issue(1, 1); CP_COMMIT();
    issue(2, 2); CP_COMMIT();
    CP_WAIT2();
    __syncthreads();

    int stidx = 0;
    for (int c = 0; c < C; c++) {
        const uint32_t stg = sbase + stidx * G1_STAGE;
        const uint32_t stgB = stg + 16384;
#pragma unroll
        for (int ks = 0; ks < 2; ks++) {
            uint32_t ah[2][4], al[2][4];
#pragma unroll
            for (int ty = 0; ty < 2; ty++) {
                int rowA = wy * 32 + ty * 16 + (lane & 15);
                int cA = ks * 2 + (lane >> 4);
                uint32_t base = stg + rowA * 128;
                ldsm_x4(ah[ty], base + ((cA ^ (rowA & 7)) * 16));
                ldsm_x4(al[ty], base + (((cA + 4) ^ (rowA & 7)) * 16));
            }
            int rowB = ks * 16 + (lane & 15);
            uint32_t bbase = stgB + rowB * 256;
            uint32_t bfr[2][8];
            {
                int cm = wx * 8 + (lane >> 4);
                uint32_t sw = ((cm & 8) | ((cm & 7) ^ (rowB & 7))) * 16;
                ldsm_x4_t(&bfr[0][0], bbase + sw);
                ldsm_x4_t(&bfr[0][4], bbase + 8192 + sw);
            }
#pragma unroll
            for (int tx = 0; tx < 4; tx++) {
                if (tx < 3) {
                    int cm = wx * 8 + (tx + 1) * 2 + (lane >> 4);
                    uint32_t sw = ((cm & 8) | ((cm & 7) ^ (rowB & 7))) * 16;
                    ldsm_x4_t(&bfr[(tx + 1) & 1][0], bbase + sw);
                    ldsm_x4_t(&bfr[(tx + 1) & 1][4], bbase + 8192 + sw);
                }
                const uint32_t* bh = &bfr[tx & 1][0];
                const uint32_t* bl = &bfr[tx & 1][4];
#pragma unroll
                for (int ty = 0; ty < 2; ty++)
#pragma unroll
                    for (int j = 0; j < 2; j++)
                        mma16816(d[ty][tx * 2 + j], ah[ty], &bh[j * 2]);
#pragma unroll
                for (int ty = 0; ty < 2; ty++)
#pragma unroll
                    for (int j = 0; j < 2; j++)
                        mma16816(d[ty][tx * 2 + j], ah[ty], &bl[j * 2]);
#pragma unroll
                for (int ty = 0; ty < 2; ty++)
#pragma unroll
                    for (int j = 0; j < 2; j++)
                        mma16816(d[ty][tx * 2 + j], al[ty], &bh[j * 2]);
            }
        }
        CP_WAIT1();
        __syncthreads();
        if (c + 3 < C) { issue(c + 3, stidx); CP_COMMIT(); }
        stidx = (stidx + 1 == 3) ? 0 : stidx + 1;
    }

    // epilogue: transpose through smem -> Zt[m][h] coalesced
    float* tb = (float*)smem;  // [128 m][132]
#pragma unroll
    for (int ty = 0; ty < 2; ty++)
#pragma unroll
        for (int t8 = 0; t8 < 8; t8++) {
            int h = wy * 32 + ty * 16 + (lane >> 2);
            int m = wx * 64 + t8 * 8 + (lane & 3) * 2;
            tb[m * 132 + h]           = d[ty][t8][0];
            tb[(m + 1) * 132 + h]     = d[ty][t8][1];
            tb[m * 132 + h + 8]       = d[ty][t8][2];
            tb[(m + 1) * 132 + h + 8] = d[ty][t8][3];
        }
    __syncthreads();
    {
        int r = tid >> 1, half = tid & 1;
        float* dst = g_Zt + (size_t)(b * MM + m0 + r) * HH + h0 + half * 64;
        const float* srcr = tb + r * 132 + half * 64;
#pragma unroll
        for (int v = 0; v < 16; v++)
            *(float4*)(dst + v * 4) = *(const float4*)(srcr + v * 4);
    }
}

// ======================= knn + interpolate fused ===========================
// phase 1: per-thread brute-force top-3 + IDW weights -> smem
// phase 2: 8 warps x 32 queries: gather Zt rows, weight, +bias, ReLU, split
__global__ __launch_bounds__(256) void knn_interp_kernel(const float* __restrict__ tgt,
                                                         const float* __restrict__ b1v) {
    __shared__ float4 srt4[MM * 3 / 4];
    __shared__ float4 srr4[MM / 4];
    __shared__ int   sidx[256 * 3];
    __shared__ float swt[256 * 3];
    const int b = blockIdx.y;
    const int tid = threadIdx.x;
    const int n = blockIdx.x * 256 + tid;
    {
        const float4* g4 = (const float4*)(g_rt + b * MM * 3);
        for (int i = tid; i < MM * 3 / 4; i += 256) srt4[i] = g4[i];
        const float4* r4 = (const float4*)(g_rr + b * MM);
        for (int i = tid; i < MM / 4; i += 256) srr4[i] = r4[i];
    }
    __syncthreads();

    {
        float q0 = tgt[(b * 3 + 0) * NN + n];
        float q1 = tgt[(b * 3 + 1) * NN + n];
        float q2 = tgt[(b * 3 + 2) * NN + n];
        float qq = (q0 * q0 + q1 * q1) + q2 * q2;
        float d0 = 1e30f, d1 = 1e30f, d2 = 1e30f;
        int i0 = 0, i1 = 0, i2 = 0;
        for (int g = 0; g < MM / 4; g++) {
            float4 a = srt4[g * 3 + 0], bq = srt4[g * 3 + 1], c = srt4[g * 3 + 2];
            float4 rr = srr4[g];
            float X[4] = {a.x, a.w, bq.z, c.y};
            float Y[4] = {a.y, bq.x, bq.w, c.z};
            float Z[4] = {a.z, bq.y, c.x, c.w};
            float RR[4] = {rr.x, rr.y, rr.z, rr.w};
#pragma unroll
            for (int p = 0; p < 4; p++) {
                float dot = q0 * X[p];
                dot = fmaf(q1, Y[p], dot);
                dot = fmaf(q2, Z[p], dot);
                float sq = (qq + RR[p]) - 2.0f * dot;
                int m = g * 4 + p;
                // strict < keeps lower index on ties (jax.lax.top_k stability)
                if (sq < d2) {
                    if (sq < d1) {
                        d2 = d1; i2 = i1;
                        if (sq < d0) { d1 = d0; i1 = i0; d0 = sq; i0 = m; }
                        else         { d1 = sq; i1 = m; }
                    } else { d2 = sq; i2 = m; }
                }
            }
        }
        const float* srt = (const float*)srt4;
        int ii[3] = {i0, i1, i2};
        float wv[3];
#pragma unroll
        for (int k = 0; k < 3; k++) {
            float dx = srt[3 * ii[k] + 0] - q0;
            float dy = srt[3 * ii[k] + 1] - q1;
            float dz = srt[3 * ii[k] + 2] - q2;
            float dist = sqrtf((dx * dx + dy * dy) + dz * dz) + 1e-8f;
            wv[k] = 1.0f / dist;
        }
        float ws = (wv[0] + wv[1]) + wv[2];
#pragma unroll
        for (int k = 0; k < 3; k++) {
            sidx[tid * 3 + k] = ii[k];
            swt[tid * 3 + k] = wv[k] / ws;
        }
    }
    __syncthreads();

    // phase 2: interpolate (warp per query, 32 queries per warp)
    const int wid = tid >> 5, lane = tid & 31;
    const float4* bb = (const float4*)b1v;
    for (int q = wid * 32; q < wid * 32 + 32; q++) {
        int nq = blockIdx.x * 256 + q;
        int i0 = sidx[q * 3 + 0], i1 = sidx[q * 3 + 1], i2 = sidx[q * 3 + 2];
        float w0 = swt[q * 3 + 0], w1 = swt[q * 3 + 1], w2 = swt[q * 3 + 2];
        const float4* z0 = (const float4*)(g_Zt + (size_t)(b * MM + i0) * HH);
        const float4* z1 = (const float4*)(g_Zt + (size_t)(b * MM + i1) * HH);
        const float4* z2 = (const float4*)(g_Zt + (size_t)(b * MM + i2) * HH);
        size_t rowoff = (size_t)(b * NN + nq) * HH;
        __nv_bfloat162* dh = (__nv_bfloat162*)(g_hhi + rowoff);
        __nv_bfloat162* dl = (__nv_bfloat162*)(g_hlo + rowoff);
#pragma unroll
        for (int r = 0; r < 3; r++) {
            int j = lane + r * 32;
            float4 a = z0[j], c = z1[j], dq = z2[j], bi = bb[j];
            float o[4];
            o[0] = fmaxf(fmaf(w2, dq.x, fmaf(w1, c.x, w0 * a.x)) + bi.x, 0.0f);
            o[1] = fmaxf(fmaf(w2, dq.y, fmaf(w1, c.y, w0 * a.y)) + bi.y, 0.0f);
            o[2] = fmaxf(fmaf(w2, dq.z, fmaf(w1, c.z, w0 * a.z)) + bi.z, 0.0f);
            o[3] = fmaxf(fmaf(w2, dq.w, fmaf(w1, c.w, w0 * a.w)) + bi.w, 0.0f);
#pragma unroll
            for (int p = 0; p < 2; p++) {
                bf16 ha = __float2bfloat16_rn(o[p * 2]), hb = __float2bfloat16_rn(o[p * 2 + 1]);
                __nv_bfloat162 hv, lv;
                hv.x = ha; hv.y = hb;
                lv.x = __float2bfloat16_rn(o[p * 2] - __bfloat162float(ha));
                lv.y = __float2bfloat16_rn(o[p * 2 + 1] - __bfloat162float(hb));
                dh[j * 2 + p] = hv;
                dl[j * 2 + p] = lv;
            }
        }
    }
}

// ======================= GEMM2 (HMMA): out = W2 @ h + b2 ===================
// (identical to round-15 passing version)
#define G2_STAGE 32768
#define G2_SMEM  (2 * G2_STAGE)
__global__ __launch_bounds__(256, 2) void gemm2_mma(const float* __restrict__ b2v,
                                                    float* __restrict__ out) {
    extern __shared__ char smem[];
    const uint32_t sbase = smem_u32(smem);
    const int tid = threadIdx.x;
    const int wid = tid >> 5, lane = tid & 31;
    const int wy = wid >> 1, wx = wid & 1;  // warp tile: 32o x 64n
    const int b = blockIdx.z;
    const int n0b = blockIdx.x * 128;

    float d[2][8][4];
#pragma unroll
    for (int ty = 0; ty < 2; ty++)
#pragma unroll
        for (int tx = 0; tx < 8; tx++)
#pragma unroll
            for (int j = 0; j < 4; j++) d[ty][tx][j] = 0.0f;

    const int C = HH / 32;  // 12 chunks

    auto issue = [&](int c, int st) {
        const int kk = c * 32;
        const uint32_t stg = sbase + st * G2_STAGE;
#pragma unroll
        for (int i = 0; i < 4; i++) {  // A: W2 hi/lo, 1024 granules
            int u = tid + i * 256;
            int row = u >> 3, g = u & 7;
            int split = g >> 2, seg = g & 3;
            const bf16* gp = (split ? g_W2lo : g_W2hi) + (size_t)row * HH + kk + seg * 8;
            CP_ASYNC16(stg + row * 128 + ((g ^ (row & 7)) * 16), gp);
        }
#pragma unroll
        for (int i = 0; i < 4; i++) {  // B: h hi/lo, 1024 granules
            int u = tid + i * 256;
            int row = u >> 3, g = u & 7;
            int split = g >> 2, seg = g & 3;
            const bf16* gp = (split ? g_hlo : g_hhi) +
                             (size_t)(b * NN + n0b + row) * HH + kk + seg * 8;
            CP_ASYNC16(stg + 16384 + row * 128 + ((g ^ (row & 7)) * 16), gp);
        }
    };

    issue(0, 0);
    CP_COMMIT();
    for (int c = 0; c < C; c++) {
        if (c + 1 < C) issue(c + 1, (c + 1) & 1);
        CP_COMMIT();
        CP_WAIT1();
        __syncthreads();
        const uint32_t stg = sbase + (c & 1) * G2_STAGE;
        const uint32_t stgB = stg + 16384;
#pragma unroll
        for (int ks = 0; ks < 2; ks++) {
            uint32_t ah[2][4], al[2][4];
#pragma unroll
            for (int ty = 0; ty < 2; ty++) {
                int rowA = wy * 32 + ty * 16 + (lane & 15);
                int cA = ks * 2 + (lane >> 4);
                uint32_t base = stg + rowA * 128;
                ldsm_x4(ah[ty], base + ((cA ^ (rowA & 7)) * 16));
                ldsm_x4(al[ty], base + (((cA + 4) ^ (rowA & 7)) * 16));
            }
#pragma unroll
            for (int tx = 0; tx < 4; tx++) {
                uint32_t bh[4], bl[4];
                int rowB = wx * 64 + tx * 16 + (lane & 7) + ((lane >> 4) << 3);
                int cB = ks * 2 + ((lane >> 3) & 1);
                uint32_t base = stgB + rowB * 128;
                ldsm_x4(bh, base + ((cB ^ (rowB & 7)) * 16));
                ldsm_x4(bl, base + (((cB + 4) ^ (rowB & 7)) * 16));
#pragma unroll
                for (int ty = 0; ty < 2; ty++)
#pragma unroll
                    for (int j = 0; j < 2; j++)
                        mma16816(d[ty][tx * 2 + j], ah[ty], &bh[j * 2]);
#pragma unroll
                for (int ty = 0; ty < 2; ty++)
#pragma unroll
                    for (int j = 0; j < 2; j++)
                        mma16816(d[ty][tx * 2 + j], ah[ty], &bl[j * 2]);
#pragma unroll
                for (int ty = 0; ty < 2; ty++)
#pragma unroll
                    for (int j = 0; j < 2; j++)
                        mma16816(d[ty][tx * 2 + j], al[ty], &bh[j * 2]);
            }
        }
        __syncthreads();
    }

#pragma unroll
    for (int ty = 0; ty < 2; ty++) {
        int o = wy * 32 + ty * 16 + (lane >> 2);
        float bias0 = b2v[o], bias1 = b2v[o + 8];
        float* r0 = out + (size_t)(b * OUT_D + o) * NN + n0b;
        float* r1 = out + (size_t)(b * OUT_D + o + 8) * NN + n0b;
#pragma unroll
        for (int t8 = 0; t8 < 8; t8++) {
            int n = wx * 64 + t8 * 8 + (lane & 3) * 2;
            float2 v0 = {d[ty][t8][0] + bias0, d[ty][t8][1] + bias0};
            float2 v1 = {d[ty][t8][2] + bias1, d[ty][t8][3] + bias1};
            *(float2*)(r0 + n) = v0;
            *(float2*)(r1 + n) = v1;
        }
    }
}

// ---------------- launcher -------------------------------------------------
// 4 launches: prep -> gemm1 -> knn_interp -> gemm2 (profiled: index 3 = gemm2)
extern "C" void kernel_launch(void* const* d_in, const int* in_sizes, int n_in,
                              void* d_out, int out_size) {
    const float* vn_feat    = (const float*)d_in[0];
    const float* vn_xyz     = (const float*)d_in[1];
    const float* target_xyz = (const float*)d_in[2];
    const float* R_align    = (const float*)d_in[3];
    const float* W1         = (const float*)d_in[4];
    const float* b1         = (const float*)d_in[5];
    const float* W2         = (const float*)d_in[6];
    const float* b2         = (const float*)d_in[7];
    float* out              = (float*)d_out;

    static bool attr_done = false;
    if (!attr_done) {
        cudaFuncSetAttribute(gemm1_mma, cudaFuncAttributeMaxDynamicSharedMemorySize, G1_SMEM);
        cudaFuncSetAttribute(gemm2_mma, cudaFuncAttributeMaxDynamicSharedMemorySize, G2_SMEM);
        attr_done = true;
    }

    prep_kernel<<<PREP_GRID, 256>>>(vn_feat, vn_xyz, W1, W2, R_align);
    gemm1_mma<<<dim3(MM / 128, HH / 128, BB), 256, G1_SMEM>>>();
    knn_interp_kernel<<<dim3(NN / 256, BB), 256>>>(target_xyz, b1);
    gemm2_mma<<<dim3(NN / 128, 1, BB), 256, G2_SMEM>>>(b2, out);
}

// round 17
// speedup vs baseline: 1.1028x; 1.1028x over previous
#include <cuda_runtime.h>
#include <cuda_bf16.h>
#include <cstdint>

#define BB 8
#define CC 256
#define MM 2048
#define NN 4096
#define C3 768
#define HH 384
#define OUT_D 128
#define KNN_K 3

typedef __nv_bfloat16 bf16;

// ---------------- device scratch ----------------
__device__ float g_rt[BB * MM * 3];
__device__ float g_rr[BB * MM];
__device__ bf16  g_Fhi[(size_t)BB * C3 * MM];
__device__ bf16  g_Flo[(size_t)BB * C3 * MM];
__device__ bf16  g_W1hi[HH * C3];
__device__ bf16  g_W1lo[HH * C3];
__device__ bf16  g_W2hi[OUT_D * HH];
__device__ bf16  g_W2lo[OUT_D * HH];
__device__ float g_Zt[BB * MM * HH];
__device__ bf16  g_hhi[(size_t)BB * NN * HH];
__device__ bf16  g_hlo[(size_t)BB * NN * HH];

// ---------------- ptx helpers (all sm_80+ baseline, no "a" features) -------
__device__ __forceinline__ uint32_t smem_u32(const void* p) {
    uint32_t a;
    asm("{ .reg .u64 t; cvta.to.shared.u64 t, %1; cvt.u32.u64 %0, t; }" : "=r"(a) : "l"(p));
    return a;
}
#define CP_ASYNC16(saddr, gptr) \
    asm volatile("cp.async.cg.shared.global [%0], [%1], 16;" :: "r"(saddr), "l"(gptr))
#define CP_COMMIT() asm volatile("cp.async.commit_group;" ::: "memory")
#define CP_WAIT1()  asm volatile("cp.async.wait_group 1;" ::: "memory")
#define CP_WAIT2()  asm volatile("cp.async.wait_group 2;" ::: "memory")

__device__ __forceinline__ void ldsm_x4(uint32_t* r, uint32_t addr) {
    asm volatile("ldmatrix.sync.aligned.m8n8.x4.shared.b16 {%0,%1,%2,%3}, [%4];"
                 : "=r"(r[0]), "=r"(r[1]), "=r"(r[2]), "=r"(r[3]) : "r"(addr));
}
__device__ __forceinline__ void ldsm_x4_t(uint32_t* r, uint32_t addr) {
    asm volatile("ldmatrix.sync.aligned.m8n8.x4.trans.shared.b16 {%0,%1,%2,%3}, [%4];"
                 : "=r"(r[0]), "=r"(r[1]), "=r"(r[2]), "=r"(r[3]) : "r"(addr));
}
__device__ __forceinline__ void mma16816(float* d, const uint32_t* a, const uint32_t* b) {
    asm volatile(
        "mma.sync.aligned.m16n8k16.row.col.f32.bf16.bf16.f32 "
        "{%0,%1,%2,%3}, {%4,%5,%6,%7}, {%8,%9}, {%0,%1,%2,%3};"
        : "+f"(d[0]), "+f"(d[1]), "+f"(d[2]), "+f"(d[3])
        : "r"(a[0]), "r"(a[1]), "r"(a[2]), "r"(a[3]), "r"(b[0]), "r"(b[1]));
}

// ======================= prep_feat: featrot (smem-staged) + weight splits ==
// block ranges: [0,4096) featrot | [4096,5248) W1 split | [5248,5440) W2 split
#define PF_FEAT_BLOCKS 4096
#define PF_W1_BLOCKS   1152
#define PF_W2_BLOCKS   192
#define PF_GRID (PF_FEAT_BLOCKS + PF_W1_BLOCKS + PF_W2_BLOCKS)
__global__ __launch_bounds__(256) void prep_feat_kernel(const float* __restrict__ vf,
                                                        const float* __restrict__ W1,
                                                        const float* __restrict__ W2,
                                                        const float* __restrict__ Rg) {
    __shared__ __nv_bfloat162 s_hi[256 * 6];  // 6 KB
    __shared__ __nv_bfloat162 s_lo[256 * 6];  // 6 KB
    const int blk = blockIdx.x;
    const int tid = threadIdx.x;
    if (blk < PF_FEAT_BLOCKS) {
        const int P0 = blk * 1024;          // 1024 points per block
        const int p0 = P0 + tid * 4;        // 4 points per thread
        const int b = p0 / (CC * MM);
        const float* R = Rg + b * 9;
        float R00 = R[0], R01 = R[1], R02 = R[2];
        float R10 = R[3], R11 = R[4], R12 = R[5];
        float R20 = R[6], R21 = R[7], R22 = R[8];
        const float4* src = (const float4*)(vf + (size_t)p0 * 3);
        float4 v0 = src[0], v1 = src[1], v2 = src[2];
        float px[4] = {v0.x, v0.w, v1.z, v2.y};
        float py[4] = {v0.y, v1.x, v1.w, v2.z};
        float pz[4] = {v0.z, v1.y, v2.x, v2.w};
        float o[12];
#pragma unroll
        for (int p = 0; p < 4; p++) {
            o[p * 3 + 0] = fmaf(pz[p], R20, fmaf(py[p], R10, px[p] * R00));
            o[p * 3 + 1] = fmaf(pz[p], R21, fmaf(py[p], R11, px[p] * R01));
            o[p * 3 + 2] = fmaf(pz[p], R22, fmaf(py[p], R12, px[p] * R02));
        }
#pragma unroll
        for (int j = 0; j < 6; j++) {
            float a = o[j * 2], bq = o[j * 2 + 1];
            bf16 ha = __float2bfloat16_rn(a), hb = __float2bfloat16_rn(bq);
            __nv_bfloat162 hv, lv;
            hv.x = ha; hv.y = hb;
            lv.x = __float2bfloat16_rn(a - __bfloat162float(ha));
            lv.y = __float2bfloat16_rn(bq - __bfloat162float(hb));
            s_hi[tid * 6 + j] = hv;
            s_lo[tid * 6 + j] = lv;
        }
        __syncthreads();
        // coalesced copy-out: 6144 B per stream = 384 uint4
        uint4* dh = (uint4*)(g_Fhi + (size_t)P0 * 3);
        uint4* dl = (uint4*)(g_Flo + (size_t)P0 * 3);
        const uint4* sh = (const uint4*)s_hi;
        const uint4* sl = (const uint4*)s_lo;
        dh[tid] = sh[tid];
        dl[tid] = sl[tid];
        if (tid < 128) {
            dh[256 + tid] = sh[256 + tid];
            dl[256 + tid] = sl[256 + tid];
        }
    } else if (blk < PF_FEAT_BLOCKS + PF_W1_BLOCKS) {
        int t = (blk - PF_FEAT_BLOCKS) * 256 + tid;  // < HH*C3 exactly
        float x = W1[t];
        bf16 h = __float2bfloat16_rn(x);
        g_W1hi[t] = h;
        g_W1lo[t] = __float2bfloat16_rn(x - __bfloat162float(h));
    } else {
        int t = (blk - PF_FEAT_BLOCKS - PF_W1_BLOCKS) * 256 + tid;  // < OUT_D*HH
        float x = W2[t];
        bf16 h = __float2bfloat16_rn(x);
        g_W2hi[t] = h;
        g_W2lo[t] = __float2bfloat16_rn(x - __bfloat162float(h));
    }
}

// ======================= prep_rot: rotate source xyz =======================
__global__ void prep_rot_kernel(const float* __restrict__ xyz, const float* __restrict__ Rg) {
    int t = blockIdx.x * blockDim.x + threadIdx.x;
    if (t >= BB * MM) return;
    int b = t / MM, m = t % MM;
    const float* R = Rg + b * 9;
    float x0 = xyz[(b * 3 + 0) * MM + m];
    float x1 = xyz[(b * 3 + 1) * MM + m];
    float x2 = xyz[(b * 3 + 2) * MM + m];
    float r0 = fmaf(x2, R[6], fmaf(x1, R[3], x0 * R[0]));
    float r1 = fmaf(x2, R[7], fmaf(x1, R[4], x0 * R[1]));
    float r2 = fmaf(x2, R[8], fmaf(x1, R[5], x0 * R[2]));
    g_rt[t * 3 + 0] = r0;
    g_rt[t * 3 + 1] = r1;
    g_rt[t * 3 + 2] = r2;
    g_rr[t] = (r0 * r0 + r1 * r1) + r2 * r2;
}

// ======================= GEMM1 (HMMA): Zt[m][h] = (W1 @ G)^T ===============
// (identical to round-15 passing version: swizzled layouts, 3-stage pipeline)
#define G1_STAGE 32768
#define G1_SMEM  (3 * G1_STAGE)
__global__ __launch_bounds__(256, 2) void gemm1_mma() {
    extern __shared__ char smem[];
    const uint32_t sbase = smem_u32(smem);
    const int tid = threadIdx.x;
    const int wid = tid >> 5, lane = tid & 31;
    const int wy = wid >> 1, wx = wid & 1;  // warp tile: 32h x 64m
    const int b = blockIdx.z;
    const int m0 = blockIdx.x * 128;
    const int h0 = blockIdx.y * 128;
    const size_t bF = (size_t)b * C3 * MM;

    float d[2][8][4];
#pragma unroll
    for (int ty = 0; ty < 2; ty++)
#pragma unroll
        for (int tx = 0; tx < 8; tx++)
#pragma unroll
            for (int j = 0; j < 4; j++) d[ty][tx][j] = 0.0f;

    const int C = C3 / 32;  // 24 chunks

    auto issue = [&](int c, int st) {
        const int kk = c * 32;
        const uint32_t stg = sbase + st * G1_STAGE;
#pragma unroll
        for (int i = 0; i < 4; i++) {  // A: W1 hi/lo, 1024 x 16B granules
            int u = tid + i * 256;
            int row = u >> 3, g = u & 7;
            int split = g >> 2, seg = g & 3;
            const bf16* gp = (split ? g_W1lo : g_W1hi) + (size_t)(h0 + row) * C3 + kk + seg * 8;
            CP_ASYNC16(stg + row * 128 + ((g ^ (row & 7)) * 16), gp);
        }
#pragma unroll
        for (int i = 0; i < 4; i++) {  // B: G hi/lo, 1024 x 16B granules
            int u = tid + i * 256;
            int split = u >> 9, idx = u & 511;
            int row = idx >> 4, cm = idx & 15;
            const bf16* gp = (split ? g_Flo : g_Fhi) + bF + (size_t)(kk + row) * MM + m0 + cm * 8;
            CP_ASYNC16(stg + 16384 + split * 8192 + row * 256 +
                       (((cm & 8) | ((cm & 7) ^ (row & 7))) * 16), gp);
        }
    };

    issue(0, 0); CP_COMMIT();
    issue(1, 1); CP_COMMIT();
    issue(2, 2); CP_COMMIT();
    CP_WAIT2();
    __syncthreads();

    int stidx = 0;
    for (int c = 0; c < C; c++) {
        const uint32_t stg = sbase + stidx * G1_STAGE;
        const uint32_t stgB = stg + 16384;
#pragma unroll
        for (int ks = 0; ks < 2; ks++) {
            uint32_t ah[2][4], al[2][4];
#pragma unroll
            for (int ty = 0; ty < 2; ty++) {
                int rowA = wy * 32 + ty * 16 + (lane & 15);
                int cA = ks * 2 + (lane >> 4);
                uint32_t base = stg + rowA * 128;
                ldsm_x4(ah[ty], base + ((cA ^ (rowA & 7)) * 16));
                ldsm_x4(al[ty], base + (((cA + 4) ^ (rowA & 7)) * 16));
            }
            int rowB = ks * 16 + (lane & 15);
            uint32_t bbase = stgB + rowB * 256;
            uint32_t bfr[2][8];
            {
                int cm = wx * 8 + (lane >> 4);
                uint32_t sw = ((cm & 8) | ((cm & 7) ^ (rowB & 7))) * 16;
                ldsm_x4_t(&bfr[0][0], bbase + sw);
                ldsm_x4_t(&bfr[0][4], bbase + 8192 + sw);
            }
#pragma unroll
            for (int tx = 0; tx < 4; tx++) {
                if (tx < 3) {
                    int cm = wx * 8 + (tx + 1) * 2 + (lane >> 4);
                    uint32_t sw = ((cm & 8) | ((cm & 7) ^ (rowB & 7))) * 16;
                    ldsm_x4_t(&bfr[(tx + 1) & 1][0], bbase + sw);
                    ldsm_x4_t(&bfr[(tx + 1) & 1][4], bbase + 8192 + sw);
                }
                const uint32_t* bh = &bfr[tx & 1][0];
                const uint32_t* bl = &bfr[tx & 1][4];
#pragma unroll
                for (int ty = 0; ty < 2; ty++)
#pragma unroll
                    for (int j = 0; j < 2; j++)
                        mma16816(d[ty][tx * 2 + j], ah[ty], &bh[j * 2]);
#pragma unroll
                for (int ty = 0; ty < 2; ty++)
#pragma unroll
                    for (int j = 0; j < 2; j++)
                        mma16816(d[ty][tx * 2 + j], ah[ty], &bl[j * 2]);
#pragma unroll
                for (int ty = 0; ty < 2; ty++)
#pragma unroll
                    for (int j = 0; j < 2; j++)
                        mma16816(d[ty][tx * 2 + j], al[ty], &bh[j * 2]);
            }
        }
        CP_WAIT1();
        __syncthreads();
        if (c + 3 < C) { issue(c + 3, stidx); CP_COMMIT(); }
        stidx = (stidx + 1 == 3) ? 0 : stidx + 1;
    }

    // epilogue: transpose through smem -> Zt[m][h] coalesced
    float* tb = (float*)smem;  // [128 m][132]
#pragma unroll
    for (int ty = 0; ty < 2; ty++)
#pragma unroll
        for (int t8 = 0; t8 < 8; t8++) {
            int h = wy * 32 + ty * 16 + (lane >> 2);
            int m = wx * 64 + t8 * 8 + (lane & 3) * 2;
            tb[m * 132 + h]           = d[ty][t8][0];
            tb[(m + 1) * 132 + h]     = d[ty][t8][1];
            tb[m * 132 + h + 8]       = d[ty][t8][2];
            tb[(m + 1) * 132 + h + 8] = d[ty][t8][3];
        }
    __syncthreads();
    {
        int r = tid >> 1, half = tid & 1;
        float* dst = g_Zt + (size_t)(b * MM + m0 + r) * HH + h0 + half * 64;
        const float* srcr = tb + r * 132 + half * 64;
#pragma unroll
        for (int v = 0; v < 16; v++)
            *(float4*)(dst + v * 4) = *(const float4*)(srcr + v * 4);
    }
}

// ======================= knn + interpolate fused ===========================
// phase 1: per-thread brute-force top-3 + IDW weights -> smem
// phase 2: warp per query (32/warp): preload 9 gather float4s (high MLP),
//          compute, pack, 8B coalesced stores.
__global__ __launch_bounds__(256) void knn_interp_kernel(const float* __restrict__ tgt,
                                                         const float* __restrict__ b1v) {
    __shared__ float4 srt4[MM * 3 / 4];
    __shared__ float4 srr4[MM / 4];
    __shared__ int   sidx[256 * 3];
    __shared__ float swt[256 * 3];
    __shared__ float sb1[HH];
    const int b = blockIdx.y;
    const int tid = threadIdx.x;
    const int n = blockIdx.x * 256 + tid;
    {
        const float4* g4 = (const float4*)(g_rt + b * MM * 3);
        for (int i = tid; i < MM * 3 / 4; i += 256) srt4[i] = g4[i];
        const float4* r4 = (const float4*)(g_rr + b * MM);
        for (int i = tid; i < MM / 4; i += 256) srr4[i] = r4[i];
        for (int i = tid; i < HH; i += 256) sb1[i] = b1v[i];
    }
    __syncthreads();

    {
        float q0 = tgt[(b * 3 + 0) * NN + n];
        float q1 = tgt[(b * 3 + 1) * NN + n];
        float q2 = tgt[(b * 3 + 2) * NN + n];
        float qq = (q0 * q0 + q1 * q1) + q2 * q2;
        float d0 = 1e30f, d1 = 1e30f, d2 = 1e30f;
        int i0 = 0, i1 = 0, i2 = 0;
        for (int g = 0; g < MM / 4; g++) {
            float4 a = srt4[g * 3 + 0], bq = srt4[g * 3 + 1], c = srt4[g * 3 + 2];
            float4 rr = srr4[g];
            float X[4] = {a.x, a.w, bq.z, c.y};
            float Y[4] = {a.y, bq.x, bq.w, c.z};
            float Z[4] = {a.z, bq.y, c.x, c.w};
            float RR[4] = {rr.x, rr.y, rr.z, rr.w};
#pragma unroll
            for (int p = 0; p < 4; p++) {
                float dot = q0 * X[p];
                dot = fmaf(q1, Y[p], dot);
                dot = fmaf(q2, Z[p], dot);
                float sq = (qq + RR[p]) - 2.0f * dot;
                int m = g * 4 + p;
                // strict < keeps lower index on ties (jax.lax.top_k stability)
                if (sq < d2) {
                    if (sq < d1) {
                        d2 = d1; i2 = i1;
                        if (sq < d0) { d1 = d0; i1 = i0; d0 = sq; i0 = m; }
                        else         { d1 = sq; i1 = m; }
                    } else { d2 = sq; i2 = m; }
                }
            }
        }
        const float* srt = (const float*)srt4;
        int ii[3] = {i0, i1, i2};
        float wv[3];
#pragma unroll
        for (int k = 0; k < 3; k++) {
            float dx = srt[3 * ii[k] + 0] - q0;
            float dy = srt[3 * ii[k] + 1] - q1;
            float dz = srt[3 * ii[k] + 2] - q2;
            float dist = sqrtf((dx * dx + dy * dy) + dz * dz) + 1e-8f;
            wv[k] = 1.0f / dist;
        }
        float ws = (wv[0] + wv[1]) + wv[2];
#pragma unroll
        for (int k = 0; k < 3; k++) {
            sidx[tid * 3 + k] = ii[k];
            swt[tid * 3 + k] = wv[k] / ws;
        }
    }
    __syncthreads();

    // phase 2: interpolate (warp per query, 32 queries per warp)
    const int wid = tid >> 5, lane = tid & 31;
    for (int q = wid * 32; q < wid * 32 + 32; q++) {
        int nq = blockIdx.x * 256 + q;
        int i0 = sidx[q * 3 + 0], i1 = sidx[q * 3 + 1], i2 = sidx[q * 3 + 2];
        float w0 = swt[q * 3 + 0], w1 = swt[q * 3 + 1], w2 = swt[q * 3 + 2];
        const float4* z0 = (const float4*)(g_Zt + (size_t)(b * MM + i0) * HH);
        const float4* z1 = (const float4*)(g_Zt + (size_t)(b * MM + i1) * HH);
        const float4* z2 = (const float4*)(g_Zt + (size_t)(b * MM + i2) * HH);
        // preload all 9 gather vectors (MLP 9)
        float4 A[3], Cc[3], Dq[3];
#pragma unroll
        for (int r = 0; r < 3; r++) {
            int j = lane + r * 32;
            A[r] = z0[j]; Cc[r] = z1[j]; Dq[r] = z2[j];
        }
        size_t rowoff = (size_t)(b * NN + nq) * HH;
        uint2* dh = (uint2*)(g_hhi + rowoff);
        uint2* dl = (uint2*)(g_hlo + rowoff);
#pragma unroll
        for (int r = 0; r < 3; r++) {
            int j = lane + r * 32;
            const float4 bi = *(const float4*)(sb1 + j * 4);
            float o[4];
            o[0] = fmaxf(fmaf(w2, Dq[r].x, fmaf(w1, Cc[r].x, w0 * A[r].x)) + bi.x, 0.0f);
            o[1] = fmaxf(fmaf(w2, Dq[r].y, fmaf(w1, Cc[r].y, w0 * A[r].y)) + bi.y, 0.0f);
            o[2] = fmaxf(fmaf(w2, Dq[r].z, fmaf(w1, Cc[r].z, w0 * A[r].z)) + bi.z, 0.0f);
            o[3] = fmaxf(fmaf(w2, Dq[r].w, fmaf(w1, Cc[r].w, w0 * A[r].w)) + bi.w, 0.0f);
            uint2 hv2, lv2;
            __nv_bfloat162 t0, t1;
            t0.x = __float2bfloat16_rn(o[0]); t0.y = __float2bfloat16_rn(o[1]);
            t1.x = __float2bfloat16_rn(o[2]); t1.y = __float2bfloat16_rn(o[3]);
            hv2.x = *(uint32_t*)&t0; hv2.y = *(uint32_t*)&t1;
            __nv_bfloat162 u0, u1;
            u0.x = __float2bfloat16_rn(o[0] - __bfloat162float(t0.x));
            u0.y = __float2bfloat16_rn(o[1] - __bfloat162float(t0.y));
            u1.x = __float2bfloat16_rn(o[2] - __bfloat162float(t1.x));
            u1.y = __float2bfloat16_rn(o[3] - __bfloat162float(t1.y));
            lv2.x = *(uint32_t*)&u0; lv2.y = *(uint32_t*)&u1;
            dh[j] = hv2;
            dl[j] = lv2;
        }
    }
}

// ======================= GEMM2 (HMMA): out = W2 @ h + b2 ===================
// (identical to round-15 passing version)
#define G2_STAGE 32768
#define G2_SMEM  (2 * G2_STAGE)
__global__ __launch_bounds__(256, 2) void gemm2_mma(const float* __restrict__ b2v,
                                                    float* __restrict__ out) {
    extern __shared__ char smem[];
    const uint32_t sbase = smem_u32(smem);
    const int tid = threadIdx.x;
    const int wid = tid >> 5, lane = tid & 31;
    const int wy = wid >> 1, wx = wid & 1;  // warp tile: 32o x 64n
    const int b = blockIdx.z;
    const int n0b = blockIdx.x * 128;

    float d[2][8][4];
#pragma unroll
    for (int ty = 0; ty < 2; ty++)
#pragma unroll
        for (int tx = 0; tx < 8; tx++)
#pragma unroll
            for (int j = 0; j < 4; j++) d[ty][tx][j] = 0.0f;

    const int C = HH / 32;  // 12 chunks

    auto issue = [&](int c, int st) {
        const int kk = c * 32;
        const uint32_t stg = sbase + st * G2_STAGE;
#pragma unroll
        for (int i = 0; i < 4; i++) {  // A: W2 hi/lo, 1024 granules
            int u = tid + i * 256;
            int row = u >> 3, g = u & 7;
            int split = g >> 2, seg = g & 3;
            const bf16* gp = (split ? g_W2lo : g_W2hi) + (size_t)row * HH + kk + seg * 8;
            CP_ASYNC16(stg + row * 128 + ((g ^ (row & 7)) * 16), gp);
        }
#pragma unroll
        for (int i = 0; i < 4; i++) {  // B: h hi/lo, 1024 granules
            int u = tid + i * 256;
            int row = u >> 3, g = u & 7;
            int split = g >> 2, seg = g & 3;
            const bf16* gp = (split ? g_hlo : g_hhi) +
                             (size_t)(b * NN + n0b + row) * HH + kk + seg * 8;
            CP_ASYNC16(stg + 16384 + row * 128 + ((g ^ (row & 7)) * 16), gp);
        }
    };

    issue(0, 0);
    CP_COMMIT();
    for (int c = 0; c < C; c++) {
        if (c + 1 < C) issue(c + 1, (c + 1) & 1);
        CP_COMMIT();
        CP_WAIT1();
        __syncthreads();
        const uint32_t stg = sbase + (c & 1) * G2_STAGE;
        const uint32_t stgB = stg + 16384;
#pragma unroll
        for (int ks = 0; ks < 2; ks++) {
            uint32_t ah[2][4], al[2][4];
#pragma unroll
            for (int ty = 0; ty < 2; ty++) {
                int rowA = wy * 32 + ty * 16 + (lane & 15);
                int cA = ks * 2 + (lane >> 4);
                uint32_t base = stg + rowA * 128;
                ldsm_x4(ah[ty], base + ((cA ^ (rowA & 7)) * 16));
                ldsm_x4(al[ty], base + (((cA + 4) ^ (rowA & 7)) * 16));
            }
#pragma unroll
            for (int tx = 0; tx < 4; tx++) {
                uint32_t bh[4], bl[4];
                int rowB = wx * 64 + tx * 16 + (lane & 7) + ((lane >> 4) << 3);
                int cB = ks * 2 + ((lane >> 3) & 1);
                uint32_t base = stgB + rowB * 128;
                ldsm_x4(bh, base + ((cB ^ (rowB & 7)) * 16));
                ldsm_x4(bl, base + (((cB + 4) ^ (rowB & 7)) * 16));
#pragma unroll
                for (int ty = 0; ty < 2; ty++)
#pragma unroll
                    for (int j = 0; j < 2; j++)
                        mma16816(d[ty][tx * 2 + j], ah[ty], &bh[j * 2]);
#pragma unroll
                for (int ty = 0; ty < 2; ty++)
#pragma unroll
                    for (int j = 0; j < 2; j++)
                        mma16816(d[ty][tx * 2 + j], ah[ty], &bl[j * 2]);
#pragma unroll
                for (int ty = 0; ty < 2; ty++)
#pragma unroll
                    for (int j = 0; j < 2; j++)
                        mma16816(d[ty][tx * 2 + j], al[ty], &bh[j * 2]);
            }
        }
        __syncthreads();
    }

#pragma unroll
    for (int ty = 0; ty < 2; ty++) {
        int o = wy * 32 + ty * 16 + (lane >> 2);
        float bias0 = b2v[o], bias1 = b2v[o + 8];
        float* r0 = out + (size_t)(b * OUT_D + o) * NN + n0b;
        float* r1 = out + (size_t)(b * OUT_D + o + 8) * NN + n0b;
#pragma unroll
        for (int t8 = 0; t8 < 8; t8++) {
            int n = wx * 64 + t8 * 8 + (lane & 3) * 2;
            float2 v0 = {d[ty][t8][0] + bias0, d[ty][t8][1] + bias0};
            float2 v1 = {d[ty][t8][2] + bias1, d[ty][t8][3] + bias1};
            *(float2*)(r0 + n) = v0;
            *(float2*)(r1 + n) = v1;
        }
    }
}

// ---------------- launcher -------------------------------------------------
// 5 launches; profiler captures launch #4 = knn_interp (the unmeasured suspect)
extern "C" void kernel_launch(void* const* d_in, const int* in_sizes, int n_in,
                              void* d_out, int out_size) {
    const float* vn_feat    = (const float*)d_in[0];
    const float* vn_xyz     = (const float*)d_in[1];
    const float* target_xyz = (const float*)d_in[2];
    const float* R_align    = (const float*)d_in[3];
    const float* W1         = (const float*)d_in[4];
    const float* b1         = (const float*)d_in[5];
    const float* W2         = (const float*)d_in[6];
    const float* b2         = (const float*)d_in[7];
    float* out              = (float*)d_out;

    static bool attr_done = false;
    if (!attr_done) {
        cudaFuncSetAttribute(gemm1_mma, cudaFuncAttributeMaxDynamicSharedMemorySize, G1_SMEM);
        cudaFuncSetAttribute(gemm2_mma, cudaFuncAttributeMaxDynamicSharedMemorySize, G2_SMEM);
        attr_done = true;
    }

    prep_feat_kernel<<<PF_GRID, 256>>>(vn_feat, W1, W2, R_align);
    prep_rot_kernel<<<(BB * MM + 255) / 256, 256>>>(vn_xyz, R_align);
    gemm1_mma<<<dim3(MM / 128, HH / 128, BB), 256, G1_SMEM>>>();
    knn_interp_kernel<<<dim3(NN / 256, BB), 256>>>(target_xyz, b1);
    gemm2_mma<<<dim3(NN / 128, 1, BB), 256, G2_SMEM>>>(b2, out);
}